// round 1
// baseline (speedup 1.0000x reference)
#include <cuda_runtime.h>

// Problem shape (fixed by reference): B=4, H=16, L=4096, D=64, S=128
#define B_ 4
#define H_ 16
#define L_ 4096
#define D_ 64
#define S_ 128

// Packed fp32x2 FMA (Blackwell FFMA2). Exact fp32 semantics per lane.
__device__ __forceinline__ void fma2(unsigned long long& acc,
                                     unsigned long long a,
                                     unsigned long long b) {
    asm("fma.rn.f32x2 %0, %1, %2, %0;" : "+l"(acc) : "l"(a), "l"(b));
}

__global__ __launch_bounds__(256, 2)
void quant_argmax_kernel(const float* __restrict__ x,
                         const float* __restrict__ c,
                         float* __restrict__ out) {
    // Codebook for this head: S_ rows x D_ cols fp32 = 32KB, as ulonglong2 (4 floats).
    // Layout: csm[s * 16 + d4]
    __shared__ ulonglong2 csm[S_ * D_ / 4];

    const int tid = threadIdx.x;
    const int bh  = blockIdx.y;          // b*H + h  (x layout [B][H][L][D])
    const int h   = bh & (H_ - 1);

    // Cooperative load of c[h] into smem (2048 x 16B, 8 iters of 256 threads).
    {
        const ulonglong2* cg =
            reinterpret_cast<const ulonglong2*>(c + (size_t)h * S_ * D_);
        #pragma unroll
        for (int i = tid; i < S_ * D_ / 4; i += 256) csm[i] = cg[i];
    }
    __syncthreads();

    // One token per lane.
    const size_t token = (size_t)bh * L_ + (size_t)blockIdx.x * 256 + tid;

    // Load x[token] (64 floats) into registers as 16 x ulonglong2
    // (each u64 = packed (x[2k], x[2k+1]) — natural f32x2 pairs over d).
    ulonglong2 xv[16];
    {
        const ulonglong2* xg =
            reinterpret_cast<const ulonglong2*>(x + token * D_);
        #pragma unroll
        for (int i = 0; i < 16; ++i) xv[i] = xg[i];
    }

    float best  = -3.402823466e38f;
    int   besti = 0;

    // 16 tiles of 8 codebook rows; keep outer loop rolled (small I$ footprint),
    // inner loops fully unrolled (384 instrs/tile body).
    #pragma unroll 1
    for (int t = 0; t < 16; ++t) {
        unsigned long long acc[8];
        #pragma unroll
        for (int j = 0; j < 8; ++j) acc[j] = 0ull;

        #pragma unroll
        for (int d4 = 0; d4 < 16; ++d4) {
            const ulonglong2 xx = xv[d4];
            #pragma unroll
            for (int j = 0; j < 8; ++j) {
                // All lanes read the same address -> smem broadcast (free).
                const ulonglong2 cc = csm[(t * 8 + j) * 16 + d4];
                fma2(acc[j], xx.x, cc.x);
                fma2(acc[j], xx.y, cc.y);
            }
        }

        #pragma unroll
        for (int j = 0; j < 8; ++j) {
            float lo, hi;
            asm("mov.b64 {%0, %1}, %2;" : "=f"(lo), "=f"(hi) : "l"(acc[j]));
            const float sc = lo + hi;
            // strict '>' with ascending scan == first-occurrence argmax (matches jnp)
            if (sc > best) { best = sc; besti = t * 8 + j; }
        }
    }

    // Cooperative one-hot write: for each of the warp's 32 tokens, the whole
    // warp writes that token's 128 floats as 32 coalesced float4 stores.
    const int    lane        = tid & 31;
    const size_t warp_token0 = token - lane;
    float4* outv = reinterpret_cast<float4*>(out);

    #pragma unroll 1
    for (int j = 0; j < 32; ++j) {
        const int idx = __shfl_sync(0xffffffffu, besti, j);
        float4 v = make_float4(0.f, 0.f, 0.f, 0.f);
        const int r = idx - lane * 4;
        if      (r == 0) v.x = 1.f;
        else if (r == 1) v.y = 1.f;
        else if (r == 2) v.z = 1.f;
        else if (r == 3) v.w = 1.f;
        outv[(warp_token0 + j) * (S_ / 4) + lane] = v;
    }
}

// Second output in the tuple: pass-through copy of c.
__global__ void copy_c_kernel(const float* __restrict__ c,
                              float* __restrict__ out) {
    const int n = H_ * S_ * D_ / 4;   // 32768 float4
    const int i = blockIdx.x * blockDim.x + threadIdx.x;
    if (i < n)
        reinterpret_cast<float4*>(out)[i] =
            reinterpret_cast<const float4*>(c)[i];
}

extern "C" void kernel_launch(void* const* d_in, const int* in_sizes, int n_in,
                              void* d_out, int out_size) {
    const float* x = (const float*)d_in[0];   // [B,H,L,D] fp32
    const float* c = (const float*)d_in[1];   // [H,S,D]  fp32
    float* out = (float*)d_out;

    dim3 grid(L_ / 256, B_ * H_);             // (16, 64) blocks, 256 thr each
    quant_argmax_kernel<<<grid, 256>>>(x, c, out);

    const size_t onehot_elems = (size_t)B_ * H_ * L_ * S_;  // 33,554,432
    const int n4 = H_ * S_ * D_ / 4;                         // 32,768
    copy_c_kernel<<<(n4 + 255) / 256, 256>>>(c, out + onehot_elems);
}

// round 2
// speedup vs baseline: 1.0033x; 1.0033x over previous
#include <cuda_runtime.h>

// Problem shape (fixed by reference): B=4, H=16, L=4096, D=64, S=128
#define B_ 4
#define H_ 16
#define L_ 4096
#define D_ 64
#define S_ 128

// Packed fp32x2 FMA (Blackwell). Exact fp32 semantics per lane.
__device__ __forceinline__ void fma2(unsigned long long& acc,
                                     unsigned long long a,
                                     unsigned long long b) {
    asm("fma.rn.f32x2 %0, %1, %2, %0;" : "+l"(acc) : "l"(a), "l"(b));
}

__global__ __launch_bounds__(256, 1)
void quant_argmax_kernel(const float* __restrict__ x,
                         const float* __restrict__ c,
                         float* __restrict__ out) {
    // Codebook for this head: 128 rows x 64 fp32 = 32KB, as ulonglong2 (4 floats).
    __shared__ ulonglong2 csm[S_ * D_ / 4];

    const int tid = threadIdx.x;
    const int bh  = blockIdx.y;          // b*H + h
    const int h   = bh & (H_ - 1);

    {
        const ulonglong2* cg =
            reinterpret_cast<const ulonglong2*>(c + (size_t)h * S_ * D_);
        #pragma unroll
        for (int i = tid; i < S_ * D_ / 4; i += 256) csm[i] = cg[i];
    }

    // Fold the c pass-through copy into this kernel (blocks with x==0),
    // overlapped before the sync. 64 blocks x 512 float4 = all of c.
    if (blockIdx.x == 0) {
        float4* dst = reinterpret_cast<float4*>(out + (size_t)B_ * H_ * L_ * S_);
        const float4* src = reinterpret_cast<const float4*>(c);
        const int per = (H_ * S_ * D_ / 4) / 64;   // 512 float4 per bh-block
        #pragma unroll
        for (int i = tid; i < per; i += 256) dst[bh * per + i] = src[bh * per + i];
    }
    __syncthreads();

    // Two tokens per thread: codebook smem reads amortized over 2 tokens.
    const size_t tokenA = (size_t)bh * L_ + (size_t)blockIdx.x * 512 + tid;
    const size_t tokenB = tokenA + 256;

    // x for both tokens fully register-resident: 2 x 16 ulonglong2 = 128 regs.
    ulonglong2 xa[16], xb[16];
    {
        const ulonglong2* xga = reinterpret_cast<const ulonglong2*>(x + tokenA * D_);
        const ulonglong2* xgb = reinterpret_cast<const ulonglong2*>(x + tokenB * D_);
        #pragma unroll
        for (int i = 0; i < 16; ++i) { xa[i] = xga[i]; xb[i] = xgb[i]; }
    }

    float bestA = -3.402823466e38f, bestB = -3.402823466e38f;
    int   ia = 0, ib = 0;

    // 16 tiles of 8 codebook rows; inner body fully unrolled
    // (128 LDS.128 + 512 FFMA2 per tile), outer t-loop rolled.
    #pragma unroll 1
    for (int t = 0; t < 16; ++t) {
        unsigned long long accA[8], accB[8];
        #pragma unroll
        for (int j = 0; j < 8; ++j) { accA[j] = 0ull; accB[j] = 0ull; }

        #pragma unroll
        for (int d4 = 0; d4 < 16; ++d4) {
            const ulonglong2 a = xa[d4];
            const ulonglong2 b = xb[d4];
            #pragma unroll
            for (int j = 0; j < 8; ++j) {
                // uniform address across the warp -> smem broadcast
                const ulonglong2 cc = csm[(t * 8 + j) * 16 + d4];
                fma2(accA[j], a.x, cc.x);
                fma2(accA[j], a.y, cc.y);
                fma2(accB[j], b.x, cc.x);
                fma2(accB[j], b.y, cc.y);
            }
        }

        #pragma unroll
        for (int j = 0; j < 8; ++j) {
            float lo, hi;
            asm("mov.b64 {%0, %1}, %2;" : "=f"(lo), "=f"(hi) : "l"(accA[j]));
            float s = lo + hi;
            if (s > bestA) { bestA = s; ia = t * 8 + j; }
            asm("mov.b64 {%0, %1}, %2;" : "=f"(lo), "=f"(hi) : "l"(accB[j]));
            s = lo + hi;
            if (s > bestB) { bestB = s; ib = t * 8 + j; }
        }
    }

    // Cooperative one-hot writes: one coalesced float4 row per token.
    const int    lane = tid & 31;
    float4* outv = reinterpret_cast<float4*>(out);

    {
        const size_t wt0 = tokenA - lane;
        #pragma unroll 1
        for (int j = 0; j < 32; ++j) {
            const int idx = __shfl_sync(0xffffffffu, ia, j);
            float4 v = make_float4(0.f, 0.f, 0.f, 0.f);
            const int r = idx - lane * 4;
            if      (r == 0) v.x = 1.f;
            else if (r == 1) v.y = 1.f;
            else if (r == 2) v.z = 1.f;
            else if (r == 3) v.w = 1.f;
            outv[(wt0 + j) * (S_ / 4) + lane] = v;
        }
    }
    {
        const size_t wt0 = tokenB - lane;
        #pragma unroll 1
        for (int j = 0; j < 32; ++j) {
            const int idx = __shfl_sync(0xffffffffu, ib, j);
            float4 v = make_float4(0.f, 0.f, 0.f, 0.f);
            const int r = idx - lane * 4;
            if      (r == 0) v.x = 1.f;
            else if (r == 1) v.y = 1.f;
            else if (r == 2) v.z = 1.f;
            else if (r == 3) v.w = 1.f;
            outv[(wt0 + j) * (S_ / 4) + lane] = v;
        }
    }
}

extern "C" void kernel_launch(void* const* d_in, const int* in_sizes, int n_in,
                              void* d_out, int out_size) {
    const float* x = (const float*)d_in[0];   // [B,H,L,D] fp32
    const float* c = (const float*)d_in[1];   // [H,S,D]  fp32
    float* out = (float*)d_out;

    dim3 grid(L_ / 512, B_ * H_);             // (8, 64) blocks, 256 thr, 2 tok/thr
    quant_argmax_kernel<<<grid, 256>>>(x, c, out);
}

// round 4
// speedup vs baseline: 1.1085x; 1.1048x over previous
#include <cuda_runtime.h>
#include <cstdint>

// Problem shape: B=4, H=16, L=4096, D=64, S=128
#define B_ 4
#define H_ 16
#define L_ 4096
#define D_ 64
#define S_ 128

#define GAP_THRESH 2e-3f

// ---------- device scratch: precomputed bf16 splits of c, swizzled ----------
// layout per head: 128 rows x 128B (64 bf16), SW128-swizzled, = 1024 uint4
__device__ uint4 g_c_split[2][H_][1024];

__device__ __forceinline__ uint32_t smem_to_u32(const void* p) {
    uint32_t a;
    asm("{ .reg .u64 t; cvta.to.shared.u64 t, %1; cvt.u32.u64 %0, t; }"
        : "=r"(a) : "l"(p));
    return a;
}
__device__ __forceinline__ unsigned short bf16_rn(float f) {
    unsigned short u; asm("cvt.rn.bf16.f32 %0, %1;" : "=h"(u) : "f"(f)); return u;
}
__device__ __forceinline__ float bf16_f32(unsigned short u) {
    return __uint_as_float(((uint32_t)u) << 16);
}
__device__ __forceinline__ uint32_t swz(uint32_t off) {   // SW128, 16B granules
    return off ^ ((off >> 3) & 0x70);
}

__device__ __forceinline__ void ldsm_x4(uint32_t a, uint32_t r[4]) {
    asm volatile("ldmatrix.sync.aligned.m8n8.x4.shared.b16 {%0,%1,%2,%3}, [%4];"
                 : "=r"(r[0]), "=r"(r[1]), "=r"(r[2]), "=r"(r[3]) : "r"(a));
}
__device__ __forceinline__ void ldsm_x2(uint32_t a, uint32_t r[2]) {
    asm volatile("ldmatrix.sync.aligned.m8n8.x2.shared.b16 {%0,%1}, [%2];"
                 : "=r"(r[0]), "=r"(r[1]) : "r"(a));
}
__device__ __forceinline__ void mma_bf16(float d[4], const uint32_t a[4],
                                         const uint32_t b[2]) {
    asm volatile(
        "mma.sync.aligned.m16n8k16.row.col.f32.bf16.bf16.f32 "
        "{%0,%1,%2,%3}, {%4,%5,%6,%7}, {%8,%9}, {%0,%1,%2,%3};"
        : "+f"(d[0]), "+f"(d[1]), "+f"(d[2]), "+f"(d[3])
        : "r"(a[0]), "r"(a[1]), "r"(a[2]), "r"(a[3]), "r"(b[0]), "r"(b[1]));
}

// Pack 8 floats -> two uint4 chunks (hi bf16 x8, lo bf16 x8)
__device__ __forceinline__ void split8(const float f[8], uint4& hi, uint4& lo) {
    uint32_t w1[4], w2[4];
    #pragma unroll
    for (int k = 0; k < 4; ++k) {
        unsigned short a1 = bf16_rn(f[2*k]);
        unsigned short a2 = bf16_rn(f[2*k]   - bf16_f32(a1));
        unsigned short b1 = bf16_rn(f[2*k+1]);
        unsigned short b2 = bf16_rn(f[2*k+1] - bf16_f32(b1));
        w1[k] = (uint32_t)a1 | ((uint32_t)b1 << 16);
        w2[k] = (uint32_t)a2 | ((uint32_t)b2 << 16);
    }
    hi = make_uint4(w1[0], w1[1], w1[2], w1[3]);
    lo = make_uint4(w2[0], w2[1], w2[2], w2[3]);
}

// ---------------- kernel 1: precompute bf16 splits of c ----------------
__global__ void presplit_c_kernel(const float* __restrict__ c) {
    const int chunk = blockIdx.x * 256 + threadIdx.x;   // 16384 chunks total
    const int h  = chunk >> 10;
    const int cr = (chunk >> 3) & 127;                  // code row
    const int cc = chunk & 7;                           // 16B chunk in row
    float f[8];
    const float4* src = reinterpret_cast<const float4*>(
        c + (size_t)h * S_ * D_ + cr * 64 + cc * 8);
    float4 v0 = src[0], v1 = src[1];
    f[0]=v0.x; f[1]=v0.y; f[2]=v0.z; f[3]=v0.w;
    f[4]=v1.x; f[5]=v1.y; f[6]=v1.z; f[7]=v1.w;
    uint4 hi, lo;
    split8(f, hi, lo);
    const uint32_t idx = swz((uint32_t)(cr * 128 + cc * 16)) >> 4;
    g_c_split[0][h][idx] = hi;
    g_c_split[1][h][idx] = lo;
}

// ---------------- smem layout (dynamic) ----------------
#define SM_X1     0          // 16KB  x hi
#define SM_X2     16384      // 16KB  x lo
#define SM_C1     32768      // 16KB  c hi
#define SM_C2     49152      // 16KB  c lo
#define SM_CFP    65536      // 32KB  c fp32
#define SM_S1     98304      // 2*128 f32
#define SM_I1     99328      // 2*128 i32
#define SM_S2     100352     // 2*128 f32
#define SM_FIDX   101376     // 128 i32
#define SM_FLAGS  101888     // 128 i32
#define SM_NFLAG  102400
#define SM_TOTAL  102528

__global__ __launch_bounds__(256, 2)
void quant_hmma_kernel(const float* __restrict__ x,
                       const float* __restrict__ c,
                       float* __restrict__ out) {
    extern __shared__ char smem[];
    const uint32_t sb = smem_to_u32(smem);
    const int tid = threadIdx.x, wid = tid >> 5, lane = tid & 31;
    const int bh = blockIdx.y, h = bh & (H_ - 1);
    const size_t tok0 = (size_t)bh * L_ + (size_t)blockIdx.x * 128;

    float* sm_s1  = reinterpret_cast<float*>(smem + SM_S1);
    int*   sm_i1  = reinterpret_cast<int*>(smem + SM_I1);
    float* sm_s2  = reinterpret_cast<float*>(smem + SM_S2);
    int*   sm_fi  = reinterpret_cast<int*>(smem + SM_FIDX);
    int*   sm_fl  = reinterpret_cast<int*>(smem + SM_FLAGS);
    int*   sm_nf  = reinterpret_cast<int*>(smem + SM_NFLAG);
    float* sm_cfp = reinterpret_cast<float*>(smem + SM_CFP);

    if (tid == 0) *sm_nf = 0;

    // --- copy precomputed c splits (already swizzled) into smem ---
    {
        uint4* d1 = reinterpret_cast<uint4*>(smem + SM_C1);
        uint4* d2 = reinterpret_cast<uint4*>(smem + SM_C2);
        #pragma unroll
        for (int i = tid; i < 1024; i += 256) {
            d1[i] = g_c_split[0][h][i];
            d2[i] = g_c_split[1][h][i];
        }
        // c fp32 for rescore
        uint4* df = reinterpret_cast<uint4*>(smem + SM_CFP);
        const uint4* sf = reinterpret_cast<const uint4*>(c + (size_t)h * S_ * D_);
        #pragma unroll
        for (int i = tid; i < 2048; i += 256) df[i] = sf[i];
    }

    // --- c pass-through copy to out tail (first x-block of each bh) ---
    if (blockIdx.x == 0) {
        float4* dst = reinterpret_cast<float4*>(out + (size_t)B_ * H_ * L_ * S_);
        const float4* src = reinterpret_cast<const float4*>(c);
        #pragma unroll
        for (int i = tid; i < 512; i += 256) dst[bh * 512 + i] = src[bh * 512 + i];
    }

    // --- split x tile [128 x 64] into bf16 hi/lo, swizzled smem ---
    {
        const float* xg = x + tok0 * D_;
        #pragma unroll
        for (int it = 0; it < 4; ++it) {
            const int j = tid + it * 256;              // 1024 chunks
            const int row = j >> 3, cc = j & 7;
            float f[8];
            const float4* src =
                reinterpret_cast<const float4*>(xg + row * 64 + cc * 8);
            float4 v0 = src[0], v1 = src[1];
            f[0]=v0.x; f[1]=v0.y; f[2]=v0.z; f[3]=v0.w;
            f[4]=v1.x; f[5]=v1.y; f[6]=v1.z; f[7]=v1.w;
            uint4 hi, lo;
            split8(f, hi, lo);
            const uint32_t off = swz((uint32_t)(row * 128 + cc * 16));
            *reinterpret_cast<uint4*>(smem + SM_X1 + off) = hi;
            *reinterpret_cast<uint4*>(smem + SM_X2 + off) = lo;
        }
    }
    __syncthreads();

    // --- MMA: warp w -> tokens [32*(w>>1), +32), codes [64*(w&1), +64) ---
    const int tb = wid >> 1;            // token block (0..3)
    const int ch = wid & 1;             // code half (0..1)

    float d[2][8][4];
    #pragma unroll
    for (int m = 0; m < 2; ++m)
        #pragma unroll
        for (int nb = 0; nb < 8; ++nb)
            #pragma unroll
            for (int q = 0; q < 4; ++q) d[m][nb][q] = 0.f;

    const uint32_t apass[3] = {sb + SM_X1, sb + SM_X1, sb + SM_X2};
    const uint32_t bpass[3] = {sb + SM_C1, sb + SM_C2, sb + SM_C1};

    // ldmatrix lane-address components
    const int arow = lane & 15;            // row within 16-row tile
    const int acol = lane >> 4;            // 16B-chunk select (0/1)
    const int brow = lane & 7;
    const int bcol = (lane >> 3) & 1;

    #pragma unroll
    for (int p = 0; p < 3; ++p) {
        const uint32_t ab = apass[p], bb = bpass[p];
        #pragma unroll
        for (int k = 0; k < 4; ++k) {
            uint32_t afrag[2][4];
            #pragma unroll
            for (int m = 0; m < 2; ++m) {
                const int r = tb * 32 + m * 16 + arow;
                ldsm_x4(ab + swz((uint32_t)(r * 128 + (2*k + acol) * 16)),
                        afrag[m]);
            }
            #pragma unroll
            for (int nb = 0; nb < 8; ++nb) {
                uint32_t bfrag[2];
                const int cr = ch * 64 + nb * 8 + brow;
                ldsm_x2(bb + swz((uint32_t)(cr * 128 + (2*k + bcol) * 16)),
                        bfrag);
                mma_bf16(d[0][nb], afrag[0], bfrag);
                mma_bf16(d[1][nb], afrag[1], bfrag);
            }
        }
    }

    // --- per-thread top2 over its 16 scores per token (4 tokens/thread) ---
    const int g   = (lane >> 2) & 7;
    const int tig = lane & 3;
    float s1[4], s2[4];
    int   i1[4];
    #pragma unroll
    for (int m = 0; m < 2; ++m) {
        #pragma unroll
        for (int r = 0; r < 2; ++r) {
            const int t = m * 2 + r;
            s1[t] = -3.402823466e38f; s2[t] = -3.402823466e38f; i1[t] = 0;
            #pragma unroll
            for (int nb = 0; nb < 8; ++nb) {
                #pragma unroll
                for (int col = 0; col < 2; ++col) {
                    const float s = d[m][nb][2*r + col];
                    const int   ix = ch * 64 + nb * 8 + 2 * tig + col;
                    if (s > s1[t]) { s2[t] = s1[t]; s1[t] = s; i1[t] = ix; }
                    else if (s > s2[t]) s2[t] = s;
                }
            }
        }
    }
    // quad merge (lanes with same g: 4g..4g+3)
    #pragma unroll
    for (int off = 1; off <= 2; off <<= 1) {
        #pragma unroll
        for (int t = 0; t < 4; ++t) {
            const float os1 = __shfl_xor_sync(0xffffffffu, s1[t], off);
            const int   oi1 = __shfl_xor_sync(0xffffffffu, i1[t], off);
            const float os2 = __shfl_xor_sync(0xffffffffu, s2[t], off);
            const bool better = (os1 > s1[t]) || (os1 == s1[t] && oi1 < i1[t]);
            if (better) { s2[t] = fmaxf(s1[t], os2); s1[t] = os1; i1[t] = oi1; }
            else        { s2[t] = fmaxf(s2[t], os1); }
        }
    }
    if (tig == 0) {
        #pragma unroll
        for (int m = 0; m < 2; ++m)
            #pragma unroll
            for (int r = 0; r < 2; ++r) {
                const int t = m * 2 + r;
                const int trow = tb * 32 + m * 16 + g + 8 * r;
                sm_s1[ch * 128 + trow] = s1[t];
                sm_i1[ch * 128 + trow] = i1[t];
                sm_s2[ch * 128 + trow] = s2[t];
            }
    }
    __syncthreads();

    // --- merge code halves, flag small gaps ---
    if (tid < 128) {
        const float a1 = sm_s1[tid],       b1 = sm_s1[128 + tid];
        const int   ai = sm_i1[tid],       bi = sm_i1[128 + tid];
        const float a2 = sm_s2[tid],       b2 = sm_s2[128 + tid];
        float f1, f2; int fi;
        const bool abet = (a1 > b1) || (a1 == b1 && ai < bi);
        if (abet) { f1 = a1; fi = ai; f2 = fmaxf(a2, b1); }
        else      { f1 = b1; fi = bi; f2 = fmaxf(b2, a1); }
        sm_fi[tid] = fi;
        if (f1 - f2 < GAP_THRESH) {
            const int pos = atomicAdd(sm_nf, 1);
            sm_fl[pos] = tid;
        }
    }
    __syncthreads();

    // --- exact fp32 rescore of flagged tokens (cold path) ---
    const int nf = *sm_nf;
    for (int f = wid; f < nf; f += 8) {
        const int t = sm_fl[f];
        const float* xg = x + (tok0 + t) * D_;
        float best = -3.402823466e38f;
        int   bi2 = 0;
        #pragma unroll 1
        for (int q = 0; q < 4; ++q) {
            const int code = lane * 4 + q;
            const float* cv = sm_cfp + code * 64;
            float s = 0.f;
            #pragma unroll
            for (int dd = 0; dd < 64; ++dd) s = fmaf(xg[dd], cv[dd], s);
            if (s > best || (s == best && code < bi2)) { best = s; bi2 = code; }
        }
        #pragma unroll
        for (int off = 16; off > 0; off >>= 1) {
            const float os = __shfl_xor_sync(0xffffffffu, best, off);
            const int   oi = __shfl_xor_sync(0xffffffffu, bi2, off);
            if (os > best || (os == best && oi < bi2)) { best = os; bi2 = oi; }
        }
        if (lane == 0) sm_fi[t] = bi2;
    }
    __syncthreads();

    // --- one-hot write: warp w -> tokens [16w, 16w+16), coalesced float4 ---
    float4* outv = reinterpret_cast<float4*>(out);
    #pragma unroll 1
    for (int j = 0; j < 16; ++j) {
        const int t = wid * 16 + j;
        const int idx = sm_fi[t];            // smem broadcast
        float4 v = make_float4(0.f, 0.f, 0.f, 0.f);
        const int r = idx - lane * 4;
        if      (r == 0) v.x = 1.f;
        else if (r == 1) v.y = 1.f;
        else if (r == 2) v.z = 1.f;
        else if (r == 3) v.w = 1.f;
        outv[(tok0 + t) * (S_ / 4) + lane] = v;
    }
}

extern "C" void kernel_launch(void* const* d_in, const int* in_sizes, int n_in,
                              void* d_out, int out_size) {
    const float* x = (const float*)d_in[0];   // [B,H,L,D] fp32
    const float* c = (const float*)d_in[1];   // [H,S,D]  fp32
    float* out = (float*)d_out;

    presplit_c_kernel<<<64, 256>>>(c);

    cudaFuncSetAttribute(quant_hmma_kernel,
                         cudaFuncAttributeMaxDynamicSharedMemorySize, SM_TOTAL);
    dim3 grid(L_ / 128, B_ * H_);             // (32, 64) = 2048 CTAs
    quant_hmma_kernel<<<grid, 256, SM_TOTAL>>>(x, c, out);
}

// round 5
// speedup vs baseline: 1.3522x; 1.2198x over previous
#include <cuda_runtime.h>
#include <cstdint>

// Problem shape: B=4, H=16, L=4096, D=64, S=128
#define B_ 4
#define H_ 16
#define L_ 4096
#define D_ 64
#define S_ 128

__device__ __forceinline__ uint32_t smem_to_u32(const void* p) {
    uint32_t a;
    asm("{ .reg .u64 t; cvta.to.shared.u64 t, %1; cvt.u32.u64 %0, t; }"
        : "=r"(a) : "l"(p));
    return a;
}
__device__ __forceinline__ unsigned short bf16_rn(float f) {
    unsigned short u; asm("cvt.rn.bf16.f32 %0, %1;" : "=h"(u) : "f"(f)); return u;
}
__device__ __forceinline__ float bf16_f32(unsigned short u) {
    return __uint_as_float(((uint32_t)u) << 16);
}
__device__ __forceinline__ uint32_t swz(uint32_t off) {   // SW128, 16B granules
    return off ^ ((off >> 3) & 0x70);
}
__device__ __forceinline__ void ldsm_x4(uint32_t a, uint32_t r[4]) {
    asm volatile("ldmatrix.sync.aligned.m8n8.x4.shared.b16 {%0,%1,%2,%3}, [%4];"
                 : "=r"(r[0]), "=r"(r[1]), "=r"(r[2]), "=r"(r[3]) : "r"(a));
}
__device__ __forceinline__ void mma_bf16(float d[4], const uint32_t a[4],
                                         uint32_t b0, uint32_t b1) {
    asm volatile(
        "mma.sync.aligned.m16n8k16.row.col.f32.bf16.bf16.f32 "
        "{%0,%1,%2,%3}, {%4,%5,%6,%7}, {%8,%9}, {%0,%1,%2,%3};"
        : "+f"(d[0]), "+f"(d[1]), "+f"(d[2]), "+f"(d[3])
        : "r"(a[0]), "r"(a[1]), "r"(a[2]), "r"(a[3]), "r"(b0), "r"(b1));
}
// Pack 8 floats -> hi-bf16 uint4 and lo-bf16 uint4
__device__ __forceinline__ void split8(const float f[8], uint4& hi, uint4& lo) {
    uint32_t w1[4], w2[4];
    #pragma unroll
    for (int k = 0; k < 4; ++k) {
        unsigned short a1 = bf16_rn(f[2*k]);
        unsigned short a2 = bf16_rn(f[2*k]   - bf16_f32(a1));
        unsigned short b1 = bf16_rn(f[2*k+1]);
        unsigned short b2 = bf16_rn(f[2*k+1] - bf16_f32(b1));
        w1[k] = (uint32_t)a1 | ((uint32_t)b1 << 16);
        w2[k] = (uint32_t)a2 | ((uint32_t)b2 << 16);
    }
    hi = make_uint4(w1[0], w1[1], w1[2], w1[3]);
    lo = make_uint4(w2[0], w2[1], w2[2], w2[3]);
}

// ---------------- smem layout (bytes) ----------------
#define SM_X1     0          // 16KB  x hi (SW128)
#define SM_X2     16384      // 16KB  x lo (SW128)
#define SM_C1     32768      // 16KB  c hi (SW128)
#define SM_CFP    49152      // 33280B c fp32, stride 65 floats/row
#define SM_XN2    82432      // 128 f32  per-token ||x||^2
#define SM_S1     82944      // 2*128 f32
#define SM_I1     83968      // 2*128 i32
#define SM_S2     84992      // 2*128 f32
#define SM_FIDX   86016      // 128 i32
#define SM_FLAGS  86528      // 128 i32
#define SM_NFLAG  87040
#define SM_TOTAL  87056

__global__ __launch_bounds__(256, 2)
void quant_hmma_kernel(const float* __restrict__ x,
                       const float* __restrict__ c,
                       float* __restrict__ out) {
    extern __shared__ char smem[];
    const uint32_t sb = smem_to_u32(smem);
    const int tid = threadIdx.x, wid = tid >> 5, lane = tid & 31;
    const int bh = blockIdx.y, h = bh & (H_ - 1);
    const size_t tok0 = (size_t)bh * L_ + (size_t)blockIdx.x * 128;

    float* sm_xn2 = reinterpret_cast<float*>(smem + SM_XN2);
    float* sm_s1  = reinterpret_cast<float*>(smem + SM_S1);
    int*   sm_i1  = reinterpret_cast<int*>(smem + SM_I1);
    float* sm_s2  = reinterpret_cast<float*>(smem + SM_S2);
    int*   sm_fi  = reinterpret_cast<int*>(smem + SM_FIDX);
    int*   sm_fl  = reinterpret_cast<int*>(smem + SM_FLAGS);
    int*   sm_nf  = reinterpret_cast<int*>(smem + SM_NFLAG);
    float* sm_cfp = reinterpret_cast<float*>(smem + SM_CFP);

    if (tid == 0) *sm_nf = 0;

    // --- c pass-through copy to out tail (first x-block of each bh) ---
    if (blockIdx.x == 0) {
        float4* dst = reinterpret_cast<float4*>(out + (size_t)B_ * H_ * L_ * S_);
        const float4* src = reinterpret_cast<const float4*>(c);
        #pragma unroll
        for (int i = tid; i < 512; i += 256) dst[bh * 512 + i] = src[bh * 512 + i];
    }

    // --- load c[h]: fp32 -> CFP (stride 65) + hi bf16 -> C1 (SW128) ---
    {
        const float* cg = c + (size_t)h * S_ * D_;
        #pragma unroll
        for (int it = 0; it < 4; ++it) {
            const int j = tid + it * 256;          // 1024 chunks of 8 floats
            const int row = j >> 3, cc = j & 7;
            float f[8];
            const float4* src = reinterpret_cast<const float4*>(cg + row * 64 + cc * 8);
            float4 v0 = src[0], v1 = src[1];
            f[0]=v0.x; f[1]=v0.y; f[2]=v0.z; f[3]=v0.w;
            f[4]=v1.x; f[5]=v1.y; f[6]=v1.z; f[7]=v1.w;
            uint4 hi, lo;
            split8(f, hi, lo);
            *reinterpret_cast<uint4*>(smem + SM_C1 + swz((uint32_t)(row*128 + cc*16))) = hi;
            float* dstf = sm_cfp + row * 65 + cc * 8;
            #pragma unroll
            for (int e = 0; e < 8; ++e) dstf[e] = f[e];
        }
    }

    // --- split x tile [128 x 64] into bf16 hi/lo + per-token ||x||^2 ---
    {
        const float* xg = x + tok0 * D_;
        #pragma unroll
        for (int it = 0; it < 4; ++it) {
            const int j = tid + it * 256;
            const int row = j >> 3, cc = j & 7;
            float f[8];
            const float4* src = reinterpret_cast<const float4*>(xg + row * 64 + cc * 8);
            float4 v0 = src[0], v1 = src[1];
            f[0]=v0.x; f[1]=v0.y; f[2]=v0.z; f[3]=v0.w;
            f[4]=v1.x; f[5]=v1.y; f[6]=v1.z; f[7]=v1.w;
            float nrm = 0.f;
            #pragma unroll
            for (int e = 0; e < 8; ++e) nrm = fmaf(f[e], f[e], nrm);
            // reduce over the 8 lanes sharing this token row
            nrm += __shfl_xor_sync(0xffffffffu, nrm, 1);
            nrm += __shfl_xor_sync(0xffffffffu, nrm, 2);
            nrm += __shfl_xor_sync(0xffffffffu, nrm, 4);
            if ((lane & 7) == 0) sm_xn2[row] = nrm;
            uint4 hi, lo;
            split8(f, hi, lo);
            const uint32_t off = swz((uint32_t)(row*128 + cc*16));
            *reinterpret_cast<uint4*>(smem + SM_X1 + off) = hi;
            *reinterpret_cast<uint4*>(smem + SM_X2 + off) = lo;
        }
    }
    __syncthreads();

    // --- MMA: warp -> tokens [32*(wid>>1), +32), codes [64*(wid&1), +64) ---
    const int tb = wid >> 1;
    const int ch = wid & 1;

    float d[2][8][4];
    #pragma unroll
    for (int m = 0; m < 2; ++m)
        #pragma unroll
        for (int nb = 0; nb < 8; ++nb)
            #pragma unroll
            for (int q = 0; q < 4; ++q) d[m][nb][q] = 0.f;

    const int arow = lane & 15, acol = lane >> 4;
    // B x4 over nb-pairs: rows = ch*64 + nbp*16 + (lane>>4)*8 + (lane&7)
    const int brow_base = ch * 64 + ((lane >> 4) << 3) + (lane & 7);
    const int bcol = (lane >> 3) & 1;

    #pragma unroll
    for (int k = 0; k < 4; ++k) {
        uint32_t a1f[2][4], a2f[2][4];
        #pragma unroll
        for (int m = 0; m < 2; ++m) {
            const uint32_t aoff = swz((uint32_t)((tb*32 + m*16 + arow)*128 + (2*k + acol)*16));
            ldsm_x4(sb + SM_X1 + aoff, a1f[m]);
            ldsm_x4(sb + SM_X2 + aoff, a2f[m]);
        }
        #pragma unroll
        for (int nbp = 0; nbp < 4; ++nbp) {
            uint32_t bf[4];
            const uint32_t boff =
                swz((uint32_t)((brow_base + nbp*16)*128 + (2*k + bcol)*16));
            ldsm_x4(sb + SM_C1 + boff, bf);
            #pragma unroll
            for (int m = 0; m < 2; ++m) {
                mma_bf16(d[m][2*nbp],   a1f[m], bf[0], bf[1]);
                mma_bf16(d[m][2*nbp],   a2f[m], bf[0], bf[1]);
                mma_bf16(d[m][2*nbp+1], a1f[m], bf[2], bf[3]);
                mma_bf16(d[m][2*nbp+1], a2f[m], bf[2], bf[3]);
            }
        }
    }

    // --- per-thread top2 over 16 scores/token (4 tokens/thread) ---
    const int g = (lane >> 2) & 7, tig = lane & 3;
    float s1[4], s2[4];
    int   i1[4];
    #pragma unroll
    for (int m = 0; m < 2; ++m) {
        #pragma unroll
        for (int r = 0; r < 2; ++r) {
            const int t = m * 2 + r;
            s1[t] = -3.402823466e38f; s2[t] = -3.402823466e38f; i1[t] = 0;
            #pragma unroll
            for (int nb = 0; nb < 8; ++nb) {
                #pragma unroll
                for (int col = 0; col < 2; ++col) {
                    const float s = d[m][nb][2*r + col];
                    const int ix = ch * 64 + nb * 8 + 2 * tig + col;
                    if (s > s1[t]) { s2[t] = s1[t]; s1[t] = s; i1[t] = ix; }
                    else if (s > s2[t]) s2[t] = s;
                }
            }
        }
    }
    #pragma unroll
    for (int off = 1; off <= 2; off <<= 1) {
        #pragma unroll
        for (int t = 0; t < 4; ++t) {
            const float os1 = __shfl_xor_sync(0xffffffffu, s1[t], off);
            const int   oi1 = __shfl_xor_sync(0xffffffffu, i1[t], off);
            const float os2 = __shfl_xor_sync(0xffffffffu, s2[t], off);
            const bool better = (os1 > s1[t]) || (os1 == s1[t] && oi1 < i1[t]);
            if (better) { s2[t] = fmaxf(s1[t], os2); s1[t] = os1; i1[t] = oi1; }
            else        { s2[t] = fmaxf(s2[t], os1); }
        }
    }
    if (tig == 0) {
        #pragma unroll
        for (int m = 0; m < 2; ++m)
            #pragma unroll
            for (int r = 0; r < 2; ++r) {
                const int t = m * 2 + r;
                const int trow = tb * 32 + m * 16 + g + 8 * r;
                sm_s1[ch * 128 + trow] = s1[t];
                sm_i1[ch * 128 + trow] = i1[t];
                sm_s2[ch * 128 + trow] = s2[t];
            }
    }
    __syncthreads();

    // --- merge halves; flag tokens whose gap is within the error bound ---
    if (tid < 128) {
        const float a1 = sm_s1[tid], b1 = sm_s1[128 + tid];
        const int   ai = sm_i1[tid], bi = sm_i1[128 + tid];
        const float a2 = sm_s2[tid], b2 = sm_s2[128 + tid];
        float f1, f2; int fi;
        const bool abet = (a1 > b1) || (a1 == b1 && ai < bi);
        if (abet) { f1 = a1; fi = ai; f2 = fmaxf(a2, b1); }
        else      { f1 = b1; fi = bi; f2 = fmaxf(b2, a1); }
        sm_fi[tid] = fi;
        // |approx-exact| <= 2^-9*||x||*||c||(=1) + 2^-17||x|| + accum noise
        const float eps = 0.0021f * sqrtf(sm_xn2[tid]) + 5e-4f;
        if (f1 - f2 < 2.f * eps) {
            const int pos = atomicAdd(sm_nf, 1);
            sm_fl[pos] = tid;
        }
    }
    __syncthreads();

    // --- exact fp32 rescore of flagged tokens (conflict-free LDS) ---
    const int nf = *sm_nf;
    for (int f = wid; f < nf; f += 8) {
        const int t = sm_fl[f];
        const float4* xg4 = reinterpret_cast<const float4*>(x + (tok0 + t) * D_);
        float acc[4] = {0.f, 0.f, 0.f, 0.f};
        #pragma unroll
        for (int kk = 0; kk < 16; ++kk) {
            const float4 xv = xg4[kk];           // uniform -> broadcast
            #pragma unroll
            for (int q = 0; q < 4; ++q) {
                const float* cv = sm_cfp + (lane + 32 * q) * 65 + 4 * kk;
                acc[q] = fmaf(xv.x, cv[0], acc[q]);
                acc[q] = fmaf(xv.y, cv[1], acc[q]);
                acc[q] = fmaf(xv.z, cv[2], acc[q]);
                acc[q] = fmaf(xv.w, cv[3], acc[q]);
            }
        }
        float best = acc[0];
        int   bi2  = lane;
        #pragma unroll
        for (int q = 1; q < 4; ++q) {
            const int code = lane + 32 * q;
            if (acc[q] > best) { best = acc[q]; bi2 = code; }  // ascending idx
        }
        #pragma unroll
        for (int off = 16; off > 0; off >>= 1) {
            const float os = __shfl_xor_sync(0xffffffffu, best, off);
            const int   oi = __shfl_xor_sync(0xffffffffu, bi2, off);
            if (os > best || (os == best && oi < bi2)) { best = os; bi2 = oi; }
        }
        if (lane == 0) sm_fi[t] = bi2;
    }
    __syncthreads();

    // --- one-hot write: warp w -> tokens [16w, +16), coalesced float4 ---
    float4* outv = reinterpret_cast<float4*>(out);
    #pragma unroll 1
    for (int j = 0; j < 16; ++j) {
        const int t = wid * 16 + j;
        const int idx = sm_fi[t];
        float4 v = make_float4(0.f, 0.f, 0.f, 0.f);
        const int r = idx - lane * 4;
        if      (r == 0) v.x = 1.f;
        else if (r == 1) v.y = 1.f;
        else if (r == 2) v.z = 1.f;
        else if (r == 3) v.w = 1.f;
        outv[(tok0 + t) * (S_ / 4) + lane] = v;
    }
}

extern "C" void kernel_launch(void* const* d_in, const int* in_sizes, int n_in,
                              void* d_out, int out_size) {
    const float* x = (const float*)d_in[0];   // [B,H,L,D] fp32
    const float* c = (const float*)d_in[1];   // [H,S,D]  fp32
    float* out = (float*)d_out;

    cudaFuncSetAttribute(quant_hmma_kernel,
                         cudaFuncAttributeMaxDynamicSharedMemorySize, SM_TOTAL);
    dim3 grid(L_ / 128, B_ * H_);             // (32, 64) = 2048 CTAs
    quant_hmma_kernel<<<grid, 256, SM_TOTAL>>>(x, c, out);
}

// round 8
// speedup vs baseline: 1.4406x; 1.0654x over previous
#include <cuda_runtime.h>
#include <cstdint>

// Problem shape: B=4, H=16, L=4096, D=64, S=128
#define B_ 4
#define H_ 16
#define L_ 4096
#define D_ 64
#define S_ 128

__device__ __forceinline__ uint32_t smem_to_u32(const void* p) {
    uint32_t a;
    asm("{ .reg .u64 t; cvta.to.shared.u64 t, %1; cvt.u32.u64 %0, t; }"
        : "=r"(a) : "l"(p));
    return a;
}
__device__ __forceinline__ uint32_t swz(uint32_t off) {   // SW128, 16B granules
    return off ^ ((off >> 3) & 0x70);
}
__device__ __forceinline__ uint32_t f16x2_pack(float lo, float hi) {
    uint32_t r;
    asm("cvt.rn.f16x2.f32 %0, %1, %2;" : "=r"(r) : "f"(hi), "f"(lo));
    return r;
}
__device__ __forceinline__ void ldsm_x4(uint32_t a, uint32_t r[4]) {
    asm volatile("ldmatrix.sync.aligned.m8n8.x4.shared.b16 {%0,%1,%2,%3}, [%4];"
                 : "=r"(r[0]), "=r"(r[1]), "=r"(r[2]), "=r"(r[3]) : "r"(a));
}
__device__ __forceinline__ void mma_f16(float d[4], const uint32_t a[4],
                                        uint32_t b0, uint32_t b1) {
    asm volatile(
        "mma.sync.aligned.m16n8k16.row.col.f32.f16.f16.f32 "
        "{%0,%1,%2,%3}, {%4,%5,%6,%7}, {%8,%9}, {%0,%1,%2,%3};"
        : "+f"(d[0]), "+f"(d[1]), "+f"(d[2]), "+f"(d[3])
        : "r"(a[0]), "r"(a[1]), "r"(a[2]), "r"(a[3]), "r"(b0), "r"(b1));
}

// ---------------- smem layout (bytes) ----------------
#define SM_X1     0          // 16384  x fp16 (SW128)
#define SM_C1     16384      // 16384  c fp16 (SW128)
#define SM_CFP    32768      // 33280  c fp32, stride 65 floats/row (conflict-free)
#define SM_XN2    66048      // 128 f32
#define SM_S1     66560      // 2*128 f32
#define SM_I1     67584      // 2*128 i32
#define SM_S2     68608      // 2*128 f32
#define SM_FIDX   69632      // 128 i32
#define SM_FLAG   70144      // 128 i32 (flagged-token list)
#define SM_NF     70656      // counter
#define SM_TOTAL  70672

__global__ __launch_bounds__(256, 2)
void quant_hmma_kernel(const float* __restrict__ x,
                       const float* __restrict__ c,
                       float* __restrict__ out) {
    extern __shared__ char smem[];
    const uint32_t sb = smem_to_u32(smem);
    const int tid = threadIdx.x, wid = tid >> 5, lane = tid & 31;
    const int bh = blockIdx.y, h = bh & (H_ - 1);
    const size_t tok0 = (size_t)bh * L_ + (size_t)blockIdx.x * 128;

    float* sm_cfp = reinterpret_cast<float*>(smem + SM_CFP);
    float* sm_xn2 = reinterpret_cast<float*>(smem + SM_XN2);
    float* sm_s1  = reinterpret_cast<float*>(smem + SM_S1);
    int*   sm_i1  = reinterpret_cast<int*>(smem + SM_I1);
    float* sm_s2  = reinterpret_cast<float*>(smem + SM_S2);
    int*   sm_fi  = reinterpret_cast<int*>(smem + SM_FIDX);
    int*   sm_fl  = reinterpret_cast<int*>(smem + SM_FLAG);
    int*   sm_nf  = reinterpret_cast<int*>(smem + SM_NF);

    if (tid == 0) *sm_nf = 0;

    // --- c pass-through copy to out tail (first x-block of each bh) ---
    if (blockIdx.x == 0) {
        float4* dst = reinterpret_cast<float4*>(out + (size_t)B_ * H_ * L_ * S_);
        const float4* src = reinterpret_cast<const float4*>(c);
        #pragma unroll
        for (int i = tid; i < 512; i += 256) dst[bh * 512 + i] = src[bh * 512 + i];
    }

    // --- c[h]: fp32 -> fp16 SW128 smem, plus fp32 copy (stride 65) ---
    {
        const float* cg = c + (size_t)h * S_ * D_;
        #pragma unroll
        for (int it = 0; it < 4; ++it) {
            const int j = tid + it * 256;          // 1024 chunks of 8 floats
            const int row = j >> 3, cc = j & 7;
            const float4* src = reinterpret_cast<const float4*>(cg + row * 64 + cc * 8);
            const float4 v0 = src[0], v1 = src[1];
            uint4 w;
            w.x = f16x2_pack(v0.x, v0.y);
            w.y = f16x2_pack(v0.z, v0.w);
            w.z = f16x2_pack(v1.x, v1.y);
            w.w = f16x2_pack(v1.z, v1.w);
            *reinterpret_cast<uint4*>(smem + SM_C1 + swz((uint32_t)(row*128 + cc*16))) = w;
            float* dstf = sm_cfp + row * 65 + cc * 8;
            dstf[0] = v0.x; dstf[1] = v0.y; dstf[2] = v0.z; dstf[3] = v0.w;
            dstf[4] = v1.x; dstf[5] = v1.y; dstf[6] = v1.z; dstf[7] = v1.w;
        }
    }

    // --- x tile [128 x 64] -> fp16 SW128 smem + per-token ||x||^2 ---
    {
        const float* xg = x + tok0 * D_;
        #pragma unroll
        for (int it = 0; it < 4; ++it) {
            const int j = tid + it * 256;
            const int row = j >> 3, cc = j & 7;
            const float4* src = reinterpret_cast<const float4*>(xg + row * 64 + cc * 8);
            const float4 v0 = src[0], v1 = src[1];
            float nrm = v0.x*v0.x + v0.y*v0.y;
            nrm = fmaf(v0.z, v0.z, nrm); nrm = fmaf(v0.w, v0.w, nrm);
            nrm = fmaf(v1.x, v1.x, nrm); nrm = fmaf(v1.y, v1.y, nrm);
            nrm = fmaf(v1.z, v1.z, nrm); nrm = fmaf(v1.w, v1.w, nrm);
            nrm += __shfl_xor_sync(0xffffffffu, nrm, 1);
            nrm += __shfl_xor_sync(0xffffffffu, nrm, 2);
            nrm += __shfl_xor_sync(0xffffffffu, nrm, 4);
            if ((lane & 7) == 0) sm_xn2[row] = nrm;
            uint4 w;
            w.x = f16x2_pack(v0.x, v0.y);
            w.y = f16x2_pack(v0.z, v0.w);
            w.z = f16x2_pack(v1.x, v1.y);
            w.w = f16x2_pack(v1.z, v1.w);
            *reinterpret_cast<uint4*>(smem + SM_X1 + swz((uint32_t)(row*128 + cc*16))) = w;
        }
    }
    __syncthreads();

    // --- MMA: warp -> tokens [32*(wid>>1), +32), codes [64*(wid&1), +64) ---
    const int tb = wid >> 1;
    const int ch = wid & 1;

    float d[2][8][4];
    #pragma unroll
    for (int m = 0; m < 2; ++m)
        #pragma unroll
        for (int nb = 0; nb < 8; ++nb)
            #pragma unroll
            for (int q = 0; q < 4; ++q) d[m][nb][q] = 0.f;

    const int arow = lane & 15, acol = lane >> 4;
    const int brow_base = ch * 64 + ((lane >> 4) << 3) + (lane & 7);
    const int bcol = (lane >> 3) & 1;

    #pragma unroll
    for (int k = 0; k < 4; ++k) {
        uint32_t af[2][4];
        #pragma unroll
        for (int m = 0; m < 2; ++m) {
            const uint32_t aoff = swz((uint32_t)((tb*32 + m*16 + arow)*128 + (2*k + acol)*16));
            ldsm_x4(sb + SM_X1 + aoff, af[m]);
        }
        #pragma unroll
        for (int nbp = 0; nbp < 4; ++nbp) {
            uint32_t bf[4];
            const uint32_t boff =
                swz((uint32_t)((brow_base + nbp*16)*128 + (2*k + bcol)*16));
            ldsm_x4(sb + SM_C1 + boff, bf);
            #pragma unroll
            for (int m = 0; m < 2; ++m) {
                mma_f16(d[m][2*nbp],   af[m], bf[0], bf[1]);
                mma_f16(d[m][2*nbp+1], af[m], bf[2], bf[3]);
            }
        }
    }

    // --- per-thread top2 over 16 scores/token (4 tokens/thread) ---
    const int g = (lane >> 2) & 7, tig = lane & 3;
    float s1[4], s2[4];
    int   i1[4];
    #pragma unroll
    for (int m = 0; m < 2; ++m) {
        #pragma unroll
        for (int r = 0; r < 2; ++r) {
            const int t = m * 2 + r;
            s1[t] = -3.402823466e38f; s2[t] = -3.402823466e38f; i1[t] = 0;
            #pragma unroll
            for (int nb = 0; nb < 8; ++nb) {
                #pragma unroll
                for (int col = 0; col < 2; ++col) {
                    const float s = d[m][nb][2*r + col];
                    const int ix = ch * 64 + nb * 8 + 2 * tig + col;
                    if (s > s1[t]) { s2[t] = s1[t]; s1[t] = s; i1[t] = ix; }
                    else if (s > s2[t]) s2[t] = s;
                }
            }
        }
    }
    #pragma unroll
    for (int off = 1; off <= 2; off <<= 1) {
        #pragma unroll
        for (int t = 0; t < 4; ++t) {
            const float os1 = __shfl_xor_sync(0xffffffffu, s1[t], off);
            const int   oi1 = __shfl_xor_sync(0xffffffffu, i1[t], off);
            const float os2 = __shfl_xor_sync(0xffffffffu, s2[t], off);
            const bool better = (os1 > s1[t]) || (os1 == s1[t] && oi1 < i1[t]);
            if (better) { s2[t] = fmaxf(s1[t], os2); s1[t] = os1; i1[t] = oi1; }
            else        { s2[t] = fmaxf(s2[t], os1); }
        }
    }
    if (tig == 0) {
        #pragma unroll
        for (int m = 0; m < 2; ++m)
            #pragma unroll
            for (int r = 0; r < 2; ++r) {
                const int t = m * 2 + r;
                const int trow = tb * 32 + m * 16 + g + 8 * r;
                sm_s1[ch * 128 + trow] = s1[t];
                sm_i1[ch * 128 + trow] = i1[t];
                sm_s2[ch * 128 + trow] = s2[t];
            }
    }
    __syncthreads();

    // --- merge halves; build flagged-token LIST (gap < 2*eps) ---
    if (tid < 128) {
        const float a1 = sm_s1[tid], b1 = sm_s1[128 + tid];
        const int   ai = sm_i1[tid], bi = sm_i1[128 + tid];
        const float a2 = sm_s2[tid], b2 = sm_s2[128 + tid];
        float f1, f2; int fi;
        const bool abet = (a1 > b1) || (a1 == b1 && ai < bi);
        if (abet) { f1 = a1; fi = ai; f2 = fmaxf(a2, b1); }
        else      { f1 = b1; fi = bi; f2 = fmaxf(b2, a1); }
        sm_fi[tid] = fi;
        // analytic fp16 bound: 2^-10 * ||x|| * ||c||(=1); use 2x margin
        const float eps = 2.0e-3f * sqrtf(sm_xn2[tid]) + 4.0e-4f;
        if (f1 - f2 < 2.f * eps) {
            const int pos = atomicAdd(sm_nf, 1);
            sm_fl[pos] = tid;
        }
    }
    __syncthreads();

    // --- exact fp32 rescore of flagged tokens: full 128 codes/token
    //     (verbatim from the R5 kernel that benched rel_err = 0.0) ---
    const int nf = *sm_nf;
    for (int f = wid; f < nf; f += 8) {
        const int t = sm_fl[f];
        const float4* xg4 = reinterpret_cast<const float4*>(x + (tok0 + t) * D_);
        float acc[4] = {0.f, 0.f, 0.f, 0.f};
        #pragma unroll
        for (int kk = 0; kk < 16; ++kk) {
            const float4 xv = xg4[kk];           // uniform -> broadcast
            #pragma unroll
            for (int q = 0; q < 4; ++q) {
                const float* cv = sm_cfp + (lane + 32 * q) * 65 + 4 * kk;
                acc[q] = fmaf(xv.x, cv[0], acc[q]);
                acc[q] = fmaf(xv.y, cv[1], acc[q]);
                acc[q] = fmaf(xv.z, cv[2], acc[q]);
                acc[q] = fmaf(xv.w, cv[3], acc[q]);
            }
        }
        float best = acc[0];
        int   bi2  = lane;
        #pragma unroll
        for (int q = 1; q < 4; ++q) {
            const int code = lane + 32 * q;
            if (acc[q] > best) { best = acc[q]; bi2 = code; }  // ascending idx
        }
        #pragma unroll
        for (int off = 16; off > 0; off >>= 1) {
            const float os = __shfl_xor_sync(0xffffffffu, best, off);
            const int   oi = __shfl_xor_sync(0xffffffffu, bi2, off);
            if (os > best || (os == best && oi < bi2)) { best = os; bi2 = oi; }
        }
        if (lane == 0) sm_fi[t] = bi2;
    }
    __syncthreads();

    // --- one-hot write: warp w -> tokens [16w, +16), coalesced float4 ---
    float4* outv = reinterpret_cast<float4*>(out);
    #pragma unroll 1
    for (int j = 0; j < 16; ++j) {
        const int t = wid * 16 + j;
        const int idx = sm_fi[t];
        float4 v = make_float4(0.f, 0.f, 0.f, 0.f);
        const int r = idx - lane * 4;
        if      (r == 0) v.x = 1.f;
        else if (r == 1) v.y = 1.f;
        else if (r == 2) v.z = 1.f;
        else if (r == 3) v.w = 1.f;
        outv[(tok0 + t) * (S_ / 4) + lane] = v;
    }
}

extern "C" void kernel_launch(void* const* d_in, const int* in_sizes, int n_in,
                              void* d_out, int out_size) {
    const float* x = (const float*)d_in[0];   // [B,H,L,D] fp32
    const float* c = (const float*)d_in[1];   // [H,S,D]  fp32
    float* out = (float*)d_out;

    cudaFuncSetAttribute(quant_hmma_kernel,
                         cudaFuncAttributeMaxDynamicSharedMemorySize, SM_TOTAL);
    dim3 grid(L_ / 128, B_ * H_);             // (32, 64) = 2048 CTAs
    quant_hmma_kernel<<<grid, 256, SM_TOTAL>>>(x, c, out);
}